// round 2
// baseline (speedup 1.0000x reference)
#include <cuda_runtime.h>

// Problem constants
#define NFRAME 320
#define HOP    160
#define TAU    257
#define LAG    33
#define NTAU_OUT 224          // 257 - 33
#define FN     1000
#define SLEN   160000
#define EXT_LEN 576           // N + TAU - 1
#define EPS    1e-5f

// One block per (b, f) pair. 64 threads: 56 compute 4 lags each (224 lags),
// all 64 participate in loading + prefix scan.
__global__ __launch_bounds__(64)
void xcorr_kernel(const float* __restrict__ x, float* __restrict__ out)
{
    const int bf = blockIdx.x;        // bf = b * FN + f
    const int b  = bf / FN;
    const int f  = bf % FN;
    const float* __restrict__ xb = x + (size_t)b * SLEN;

    __shared__ __align__(16) float sExt[EXT_LEN];
    __shared__ float sCs[EXT_LEN + 1];   // cs[0..576], cs[j] = sum_{i<j} ext[i]^2
    __shared__ float sWsum[2];

    const int t = threadIdx.x;

    // ---- Load ext[576] (frame f ++ first 256 of frame f+1, wrap at f=999) ----
    #pragma unroll
    for (int r = 0; r < 9; r++) {
        int j = t + 64 * r;
        int idx;
        if (j < NFRAME)        idx = HOP * f + j;
        else if (f == FN - 1)  idx = j - NFRAME;           // wrap to frame 0
        else                   idx = HOP * f + j - HOP;    // frame f+1
        float v = (idx < SLEN) ? xb[idx] : 0.0f;           // zero pad tail
        sExt[j] = v;
    }
    __syncthreads();

    // ---- Prefix sum of squares: thread t owns ext[9t .. 9t+8] ----
    float loc[9];
    {
        float s = 0.0f;
        #pragma unroll
        for (int i = 0; i < 9; i++) {
            float v = sExt[9 * t + i];
            s += v * v;
            loc[i] = s;                 // inclusive within chunk
        }
        // warp inclusive scan of chunk totals
        float v = s;
        const int lane = t & 31, w = t >> 5;
        #pragma unroll
        for (int d = 1; d < 32; d <<= 1) {
            float n = __shfl_up_sync(0xffffffffu, v, d);
            if (lane >= d) v += n;
        }
        if (lane == 31) sWsum[w] = v;
        __syncthreads();
        float base = (w == 1) ? sWsum[0] : 0.0f;
        float excl = base + v - s;      // exclusive prefix of this chunk
        if (t == 0) sCs[0] = 0.0f;
        #pragma unroll
        for (int i = 0; i < 9; i++)
            sCs[9 * t + 1 + i] = excl + loc[i];
    }
    __syncthreads();

    // ---- Main loop: thread t (<56) computes lags tau = 33+4t .. 36+4t ----
    if (t < 56) {
        const float4* __restrict__ extv = (const float4*)sExt;
        const int vb = 8 + t;           // (32 + 4t)/4 : window base vector index
        float4 w0 = extv[vb];           // ext[base .. base+3], base = 32+4t

        float a0 = 0.f, a1 = 0.f, a2 = 0.f, a3 = 0.f;

        #pragma unroll 8
        for (int g = 0; g < NFRAME / 4; g++) {
            float4 nw = extv[vb + g + 1];   // ext[base+4g+4 .. +7]
            float4 fr = extv[g];            // frame[4g .. 4g+3] (broadcast)

            a0 += fr.x * w0.y;  a1 += fr.x * w0.z;  a2 += fr.x * w0.w;  a3 += fr.x * nw.x;
            a0 += fr.y * w0.z;  a1 += fr.y * w0.w;  a2 += fr.y * nw.x;  a3 += fr.y * nw.y;
            a0 += fr.z * w0.w;  a1 += fr.z * nw.x;  a2 += fr.z * nw.y;  a3 += fr.z * nw.z;
            a0 += fr.w * nw.x;  a1 += fr.w * nw.y;  a2 += fr.w * nw.z;  a3 += fr.w * nw.w;

            w0 = nw;
        }

        // ---- Normalize and store ----
        const float e0  = sCs[NFRAME];
        const int  tau0 = LAG + 4 * t;
        float4 o;
        o.x = 2.0f * a0 / (e0 + (sCs[tau0     + NFRAME] - sCs[tau0    ]) + EPS);
        o.y = 2.0f * a1 / (e0 + (sCs[tau0 + 1 + NFRAME] - sCs[tau0 + 1]) + EPS);
        o.z = 2.0f * a2 / (e0 + (sCs[tau0 + 2 + NFRAME] - sCs[tau0 + 2]) + EPS);
        o.w = 2.0f * a3 / (e0 + (sCs[tau0 + 3 + NFRAME] - sCs[tau0 + 3]) + EPS);

        float4* outv = (float4*)(out + (size_t)bf * NTAU_OUT);
        outv[t] = o;                    // 224 % 4 == 0 -> aligned
    }
}

extern "C" void kernel_launch(void* const* d_in, const int* in_sizes, int n_in,
                              void* d_out, int out_size)
{
    const float* x = (const float*)d_in[0];
    float* out = (float*)d_out;
    (void)in_sizes; (void)n_in; (void)out_size;
    xcorr_kernel<<<32 * FN, 64>>>(x, out);
}

// round 7
// speedup vs baseline: 1.1772x; 1.1772x over previous
#include <cuda_runtime.h>

#define NFRAME 320
#define HOP    160
#define TAU    257
#define LAG    33
#define NTAU_OUT 224          // 257 - 33
#define FN     1000
#define SLEN   160000
#define EXT_LEN 576           // N + TAU - 1
#define EPS    1e-5f

#define WARPS_PER_BLK 4

// One WARP per (b, f) pair. Each lane computes 7 consecutive lags:
// tau = 33 + 7*lane + k, k = 0..6.  4 warps (4 bf pairs) per block.
__global__ __launch_bounds__(32 * WARPS_PER_BLK)
void xcorr_kernel(const float* __restrict__ x, float* __restrict__ out)
{
    const int w    = threadIdx.x >> 5;          // warp in block
    const int lane = threadIdx.x & 31;
    const int bf   = blockIdx.x * WARPS_PER_BLK + w;
    const int b    = bf / FN;
    const int f    = bf % FN;
    const float* __restrict__ xb = x + (size_t)b * SLEN;

    __shared__ __align__(16) float sExt[WARPS_PER_BLK][EXT_LEN];
    __shared__ float sCs[WARPS_PER_BLK][EXT_LEN + 1];

    float* ext = sExt[w];
    float* cs  = sCs[w];

    // ---- Load ext[576]: frame f (320) ++ first 256 of frame f+1 (wrap @ f=999) ----
    #pragma unroll
    for (int r = 0; r < 18; r++) {
        int j = lane + 32 * r;
        int idx;
        if (j < NFRAME)        idx = HOP * f + j;
        else if (f == FN - 1)  idx = j - NFRAME;           // wrap to frame 0
        else                   idx = HOP * f + j - HOP;    // frame f+1
        float v = (idx < SLEN) ? xb[idx] : 0.0f;           // zero-pad tail
        ext[j] = v;
    }
    __syncwarp();

    // ---- Prefix sum of squares (per-warp): lane owns ext[18L .. 18L+17] ----
    {
        float loc[18];
        float s = 0.0f;
        #pragma unroll
        for (int i = 0; i < 18; i++) {
            float v = ext[18 * lane + i];
            s += v * v;
            loc[i] = s;
        }
        float v = s;
        #pragma unroll
        for (int d = 1; d < 32; d <<= 1) {
            float n = __shfl_up_sync(0xffffffffu, v, d);
            if (lane >= d) v += n;
        }
        float excl = v - s;                 // exclusive prefix of this chunk
        if (lane == 0) cs[0] = 0.0f;
        #pragma unroll
        for (int i = 0; i < 18; i++)
            cs[18 * lane + 1 + i] = excl + loc[i];
    }
    __syncwarp();

    // ---- Main loop: lane computes lags tau0..tau0+6, tau0 = 33 + 7*lane ----
    const int tau0 = LAG + 7 * lane;

    float win[7];                            // ext[n + tau0 .. n + tau0 + 6]
    #pragma unroll
    for (int k = 0; k < 7; k++) win[k] = ext[tau0 + k];

    float a[7];
    #pragma unroll
    for (int k = 0; k < 7; k++) a[k] = 0.0f;

    const float4* __restrict__ frv = (const float4*)ext;   // frame = ext[0:320]
    const float*  __restrict__ wsrc = ext + tau0 + 7;      // next window sample

    #pragma unroll 2
    for (int g = 0; g < NFRAME / 4; g++) {
        float4 fr = frv[g];                  // broadcast, 1 wavefront
        int base = 4 * g;

        // n = 4g + 0
        #pragma unroll
        for (int k = 0; k < 7; k++) a[k] += fr.x * win[k];
        {   float nw = wsrc[base + 0];       // stride-7 lanes: conflict-free
            #pragma unroll
            for (int k = 0; k < 6; k++) win[k] = win[k + 1];
            win[6] = nw; }

        // n = 4g + 1
        #pragma unroll
        for (int k = 0; k < 7; k++) a[k] += fr.y * win[k];
        {   float nw = wsrc[base + 1];
            #pragma unroll
            for (int k = 0; k < 6; k++) win[k] = win[k + 1];
            win[6] = nw; }

        // n = 4g + 2
        #pragma unroll
        for (int k = 0; k < 7; k++) a[k] += fr.z * win[k];
        {   float nw = wsrc[base + 2];
            #pragma unroll
            for (int k = 0; k < 6; k++) win[k] = win[k + 1];
            win[6] = nw; }

        // n = 4g + 3
        #pragma unroll
        for (int k = 0; k < 7; k++) a[k] += fr.w * win[k];
        {   float nw = wsrc[base + 3];
            #pragma unroll
            for (int k = 0; k < 6; k++) win[k] = win[k + 1];
            win[6] = nw; }
    }

    // ---- Normalize and store ----
    const float e0 = cs[NFRAME];
    float* __restrict__ o = out + (size_t)bf * NTAU_OUT + 7 * lane;
    #pragma unroll
    for (int k = 0; k < 7; k++) {
        float etau = cs[tau0 + k + NFRAME] - cs[tau0 + k];
        o[k] = 2.0f * a[k] / (e0 + etau + EPS);
    }
}

extern "C" void kernel_launch(void* const* d_in, const int* in_sizes, int n_in,
                              void* d_out, int out_size)
{
    const float* x = (const float*)d_in[0];
    float* out = (float*)d_out;
    (void)in_sizes; (void)n_in; (void)out_size;
    xcorr_kernel<<<32 * FN / WARPS_PER_BLK, 32 * WARPS_PER_BLK>>>(x, out);
}